// round 1
// baseline (speedup 1.0000x reference)
#include <cuda_runtime.h>
#include <cuda_bf16.h>
#include <cstdint>

#define MAX_N 100000
#define MAX_E 1600000
#define D 128

// Scratch (device globals -- no allocation allowed)
__device__ float g_h[(size_t)MAX_N * D];     // 51.2 MB, L2-resident
__device__ float g_si[MAX_N];
__device__ float g_sj[MAX_N];
__device__ float g_e[MAX_E + MAX_N];
__device__ float g_denom[MAX_N];

// ---------------------------------------------------------------------------
// Kernel 0: zero denom + output accumulator
// ---------------------------------------------------------------------------
__global__ void zero_kernel(float* __restrict__ out, int n) {
    int total = n * D;
    for (int i = blockIdx.x * blockDim.x + threadIdx.x; i < total;
         i += gridDim.x * blockDim.x) {
        out[i] = 0.f;
        if (i < n) g_denom[i] = 0.f;
    }
}

// ---------------------------------------------------------------------------
// Kernel 1: h = x @ W^T + b  (fp32), fused epilogue computes
//           s_i[row] = h[row]·a_i, s_j[row] = h[row]·a_j
// Block: 256 threads -> 64 rows x 128 cols. Micro-tile 8x4 per thread.
// ---------------------------------------------------------------------------
#define BM 64
#define KT 32

__global__ __launch_bounds__(256, 4)
void gemm_kernel(const float* __restrict__ x, const float* __restrict__ W,
                 const float* __restrict__ b, const float* __restrict__ Watt,
                 int n) {
    __shared__ float xs[KT][BM];    // transposed x tile: xs[k][row]
    __shared__ float ws[KT][D];     // transposed W tile: ws[k][col] = W[col][k]

    int tid = threadIdx.x;
    int tx = tid & 31;              // lane -> 4 output cols
    int ty = tid >> 5;              // warp -> 8 output rows
    int row0 = blockIdx.x * BM;

    float acc[8][4];
#pragma unroll
    for (int i = 0; i < 8; i++)
#pragma unroll
        for (int j = 0; j < 4; j++) acc[i][j] = 0.f;

    for (int kt = 0; kt < D; kt += KT) {
        // load x tile (64 x 32) as float4, store transposed
#pragma unroll
        for (int r = 0; r < 2; r++) {
            int idx = tid + r * 256;            // 0..511 float4 slots
            int row = idx >> 3;
            int c4  = (idx & 7) * 4;
            int grow = row0 + row;
            float4 v = make_float4(0.f, 0.f, 0.f, 0.f);
            if (grow < n) v = *(const float4*)&x[(size_t)grow * D + kt + c4];
            xs[c4 + 0][row] = v.x;
            xs[c4 + 1][row] = v.y;
            xs[c4 + 2][row] = v.z;
            xs[c4 + 3][row] = v.w;
        }
        // load W tile (cols 0..127, k in [kt, kt+32)) transposed
#pragma unroll
        for (int r = 0; r < 16; r++) {
            int idx = tid + r * 256;            // 0..4095
            int k = idx >> 7;
            int c = idx & 127;
            ws[k][c] = W[(size_t)c * D + kt + k];
        }
        __syncthreads();

#pragma unroll
        for (int k = 0; k < KT; k++) {
            float4 xa = *(const float4*)&xs[k][ty * 8];       // broadcast
            float4 xb = *(const float4*)&xs[k][ty * 8 + 4];
            float4 wv = *(const float4*)&ws[k][tx * 4];
            float xr[8] = {xa.x, xa.y, xa.z, xa.w, xb.x, xb.y, xb.z, xb.w};
            float wr[4] = {wv.x, wv.y, wv.z, wv.w};
#pragma unroll
            for (int i = 0; i < 8; i++)
#pragma unroll
                for (int j = 0; j < 4; j++) acc[i][j] += xr[i] * wr[j];
        }
        __syncthreads();
    }

    // epilogue: +bias, store h, fused attention projections
    float4 bv = *(const float4*)&b[tx * 4];
    float4 ai = *(const float4*)&Watt[tx * 4];
    float4 aj = *(const float4*)&Watt[D + tx * 4];

#pragma unroll
    for (int i = 0; i < 8; i++) {
        int row = row0 + ty * 8 + i;
        if (row >= n) continue;
        float4 hv = make_float4(acc[i][0] + bv.x, acc[i][1] + bv.y,
                                acc[i][2] + bv.z, acc[i][3] + bv.w);
        *(float4*)&g_h[(size_t)row * D + tx * 4] = hv;
        float psi = hv.x * ai.x + hv.y * ai.y + hv.z * ai.z + hv.w * ai.w;
        float psj = hv.x * aj.x + hv.y * aj.y + hv.z * aj.z + hv.w * aj.w;
#pragma unroll
        for (int o = 16; o; o >>= 1) {
            psi += __shfl_xor_sync(0xffffffffu, psi, o);
            psj += __shfl_xor_sync(0xffffffffu, psj, o);
        }
        if (tx == 0) { g_si[row] = psi; g_sj[row] = psj; }
    }
}

// ---------------------------------------------------------------------------
// Kernel 2: per-edge score: e = exp(leakyrelu(s_i[src]+s_j[dst]+b_att)),
//           atomic denom accumulation by src. Items [0,E) are edges,
//           [E, E+n) are self-loops.
// ---------------------------------------------------------------------------
__global__ void score_kernel(const int* __restrict__ ei,
                             const float* __restrict__ batt, int E, int n) {
    int t = blockIdx.x * blockDim.x + threadIdx.x;
    int total = E + n;
    if (t >= total) return;
    int src, dst;
    if (t < E) { src = ei[t]; dst = ei[E + t]; }
    else       { src = t - E; dst = src; }
    float sc = g_si[src] + g_sj[dst] + batt[0];
    sc = (sc >= 0.f) ? sc : 0.01f * sc;
    float e = expf(sc);
    g_e[t] = e;
    atomicAdd(&g_denom[src], e);
}

// ---------------------------------------------------------------------------
// Kernel 3: warp-per-edge aggregation: out[src] += (e/denom[src]) * h[dst]
// 512B coalesced gather of h[dst] (L2-resident) + red.global.add.v4.f32
// ---------------------------------------------------------------------------
__global__ __launch_bounds__(256)
void aggregate_kernel(const int* __restrict__ ei, float* __restrict__ out,
                      int E, int n) {
    int gw   = (blockIdx.x * blockDim.x + threadIdx.x) >> 5;
    int lane = threadIdx.x & 31;
    if (gw >= E + n) return;
    int src, dst;
    if (gw < E) { src = __ldg(&ei[gw]); dst = __ldg(&ei[E + gw]); }
    else        { src = gw - E; dst = src; }
    float alpha = g_e[gw] / g_denom[src];
    float4 hv = *(const float4*)&g_h[(size_t)dst * D + lane * 4];
    float4 m = make_float4(alpha * hv.x, alpha * hv.y,
                           alpha * hv.z, alpha * hv.w);
    float* p = &out[(size_t)src * D + lane * 4];
    asm volatile("red.global.add.v4.f32 [%0], {%1,%2,%3,%4};"
                 :: "l"(p), "f"(m.x), "f"(m.y), "f"(m.z), "f"(m.w)
                 : "memory");
}

// ---------------------------------------------------------------------------
// Kernel 4: ELU in place
// ---------------------------------------------------------------------------
__global__ void elu_kernel(float* __restrict__ out, int total) {
    int i = blockIdx.x * blockDim.x + threadIdx.x;
    if (i >= total) return;
    float v = out[i];
    out[i] = (v > 0.f) ? v : expm1f(v);
}

// ---------------------------------------------------------------------------
extern "C" void kernel_launch(void* const* d_in, const int* in_sizes, int n_in,
                              void* d_out, int out_size) {
    const float* x    = (const float*)d_in[0];
    const int*   ei   = (const int*)  d_in[1];
    const float* W    = (const float*)d_in[2];
    const float* b    = (const float*)d_in[3];
    const float* Watt = (const float*)d_in[4];
    const float* batt = (const float*)d_in[5];
    float* out = (float*)d_out;

    int n = in_sizes[0] / D;
    int E = in_sizes[1] / 2;

    int totalE = E + n;

    zero_kernel<<<(n * D + 255) / 256, 256>>>(out, n);
    gemm_kernel<<<(n + BM - 1) / BM, 256>>>(x, W, b, Watt, n);
    score_kernel<<<(totalE + 255) / 256, 256>>>(ei, batt, E, n);
    {
        long long threads = (long long)totalE * 32;
        int blocks = (int)((threads + 255) / 256);
        aggregate_kernel<<<blocks, 256>>>(ei, out, E, n);
    }
    elu_kernel<<<(n * D + 255) / 256, 256>>>(out, n * D);
}

// round 2
// speedup vs baseline: 2.5262x; 2.5262x over previous
#include <cuda_runtime.h>
#include <cuda_bf16.h>
#include <cstdint>

#define MAX_N 100000
#define MAX_E 1600000
#define D 128
#define NB_MAX 128   // max scan blocks (ceil(100000/1024)=98)

// Scratch (device globals -- no allocation allowed)
__device__ float g_h[(size_t)MAX_N * D];       // 51.2 MB, L2-resident
__device__ float g_si[MAX_N];
__device__ float g_sj[MAX_N];
__device__ int   g_cnt[MAX_N];                 // degree counts (init 1 = self loop)
__device__ int   g_offp[MAX_N];                // per-block-exclusive partial offsets
__device__ int   g_off[MAX_N + 1];             // final segment offsets
__device__ int   g_cursor[MAX_N];              // scatter cursors
__device__ int   g_bsum[NB_MAX];
__device__ int   g_bpre[NB_MAX];
__device__ int   g_ds[MAX_E + MAX_N];          // sorted dst
__device__ float g_es[MAX_E + MAX_N];          // sorted exp(score)

// ---------------------------------------------------------------------------
// init: counts start at 1 (self loop per node)
// ---------------------------------------------------------------------------
__global__ void init_kernel(int n) {
    int i = blockIdx.x * blockDim.x + threadIdx.x;
    if (i < n) g_cnt[i] = 1;
}

// ---------------------------------------------------------------------------
// GEMM: h = x @ W^T + b, fused attention projections s_i, s_j.
// 128x128 block tile, 256 threads, 8x8 micro-tile (cols split tx*4 / 64+tx*4).
// ---------------------------------------------------------------------------
#define GBM 128
#define GKT 16

__global__ __launch_bounds__(256, 2)
void gemm_kernel(const float* __restrict__ x, const float* __restrict__ W,
                 const float* __restrict__ b, const float* __restrict__ Watt,
                 int n) {
    __shared__ float xs[GKT][GBM + 4];
    __shared__ float ws[GKT][D + 4];

    int tid = threadIdx.x;
    int tx = tid & 15;          // 16 col-groups
    int ty = tid >> 4;          // 16 row-groups of 8
    int row0 = blockIdx.x * GBM;

    float acc[8][8];
#pragma unroll
    for (int i = 0; i < 8; i++)
#pragma unroll
        for (int j = 0; j < 8; j++) acc[i][j] = 0.f;

    for (int kt = 0; kt < D; kt += GKT) {
        // x tile: 128 rows x 16 k = 512 float4, 2 per thread (transposed store)
#pragma unroll
        for (int r = 0; r < 2; r++) {
            int idx = tid + r * 256;
            int row = idx >> 2;
            int k4 = (idx & 3) * 4;
            float4 v = make_float4(0.f, 0.f, 0.f, 0.f);
            int gr = row0 + row;
            if (gr < n) v = *(const float4*)&x[(size_t)gr * D + kt + k4];
            xs[k4 + 0][row] = v.x; xs[k4 + 1][row] = v.y;
            xs[k4 + 2][row] = v.z; xs[k4 + 3][row] = v.w;
        }
        // W tile: ws[k][c] = W[c][kt+k], 512 float4, 2 per thread
#pragma unroll
        for (int r = 0; r < 2; r++) {
            int idx = tid + r * 256;
            int c = idx >> 2;
            int k4 = (idx & 3) * 4;
            float4 v = *(const float4*)&W[(size_t)c * D + kt + k4];
            ws[k4 + 0][c] = v.x; ws[k4 + 1][c] = v.y;
            ws[k4 + 2][c] = v.z; ws[k4 + 3][c] = v.w;
        }
        __syncthreads();

#pragma unroll
        for (int k = 0; k < GKT; k++) {
            float4 xa = *(const float4*)&xs[k][ty * 8];
            float4 xb = *(const float4*)&xs[k][ty * 8 + 4];
            float4 w0 = *(const float4*)&ws[k][tx * 4];
            float4 w1 = *(const float4*)&ws[k][64 + tx * 4];
            float xr[8] = {xa.x, xa.y, xa.z, xa.w, xb.x, xb.y, xb.z, xb.w};
            float wr[8] = {w0.x, w0.y, w0.z, w0.w, w1.x, w1.y, w1.z, w1.w};
#pragma unroll
            for (int i = 0; i < 8; i++)
#pragma unroll
                for (int j = 0; j < 8; j++) acc[i][j] += xr[i] * wr[j];
        }
        __syncthreads();
    }

    // epilogue: bias, store h, fused attention projections (reduce over 16 lanes)
    float4 b0  = *(const float4*)&b[tx * 4];
    float4 b1  = *(const float4*)&b[64 + tx * 4];
    float4 ai0 = *(const float4*)&Watt[tx * 4];
    float4 ai1 = *(const float4*)&Watt[64 + tx * 4];
    float4 aj0 = *(const float4*)&Watt[D + tx * 4];
    float4 aj1 = *(const float4*)&Watt[D + 64 + tx * 4];

#pragma unroll
    for (int i = 0; i < 8; i++) {
        int row = row0 + ty * 8 + i;
        if (row >= n) continue;
        float4 h0 = make_float4(acc[i][0] + b0.x, acc[i][1] + b0.y,
                                acc[i][2] + b0.z, acc[i][3] + b0.w);
        float4 h1 = make_float4(acc[i][4] + b1.x, acc[i][5] + b1.y,
                                acc[i][6] + b1.z, acc[i][7] + b1.w);
        *(float4*)&g_h[(size_t)row * D + tx * 4] = h0;
        *(float4*)&g_h[(size_t)row * D + 64 + tx * 4] = h1;
        float psi = h0.x*ai0.x + h0.y*ai0.y + h0.z*ai0.z + h0.w*ai0.w
                  + h1.x*ai1.x + h1.y*ai1.y + h1.z*ai1.z + h1.w*ai1.w;
        float psj = h0.x*aj0.x + h0.y*aj0.y + h0.z*aj0.z + h0.w*aj0.w
                  + h1.x*aj1.x + h1.y*aj1.y + h1.z*aj1.z + h1.w*aj1.w;
#pragma unroll
        for (int o = 8; o; o >>= 1) {
            psi += __shfl_down_sync(0xffffffffu, psi, o, 16);
            psj += __shfl_down_sync(0xffffffffu, psj, o, 16);
        }
        if (tx == 0) { g_si[row] = psi; g_sj[row] = psj; }
    }
}

// ---------------------------------------------------------------------------
// histogram of src (counts pre-initialized to 1)
// ---------------------------------------------------------------------------
__global__ void hist_kernel(const int* __restrict__ ei, int E) {
    int t = blockIdx.x * blockDim.x + threadIdx.x;
    if (t < E) atomicAdd(&g_cnt[ei[t]], 1);
}

// ---------------------------------------------------------------------------
// 3-phase exclusive prefix scan over g_cnt[0..n)
// ---------------------------------------------------------------------------
__global__ void scan1_kernel(int n) {
    __shared__ int sh[1024];
    int i = blockIdx.x * 1024 + threadIdx.x;
    int v = (i < n) ? g_cnt[i] : 0;
    sh[threadIdx.x] = v;
    __syncthreads();
    for (int off = 1; off < 1024; off <<= 1) {
        int t = (threadIdx.x >= off) ? sh[threadIdx.x - off] : 0;
        __syncthreads();
        sh[threadIdx.x] += t;
        __syncthreads();
    }
    if (i < n) g_offp[i] = sh[threadIdx.x] - v;   // exclusive within block
    if (threadIdx.x == 1023) g_bsum[blockIdx.x] = sh[1023];
}

__global__ void scan2_kernel(int nb) {
    if (threadIdx.x == 0) {
        int acc = 0;
        for (int b = 0; b < nb; b++) { g_bpre[b] = acc; acc += g_bsum[b]; }
    }
}

__global__ void scan3_kernel(int n, int total) {
    int i = blockIdx.x * blockDim.x + threadIdx.x;
    if (i < n) {
        int o = g_offp[i] + g_bpre[i >> 10];
        g_off[i] = o;
        g_cursor[i] = o;
    }
    if (i == 0) g_off[n] = total;
}

// ---------------------------------------------------------------------------
// scatter: fused score computation + bucket placement by src
// items [0,E) are edges, [E, E+n) self-loops
// ---------------------------------------------------------------------------
__global__ void scatter_kernel(const int* __restrict__ ei,
                               const float* __restrict__ batt, int E, int n) {
    int t = blockIdx.x * blockDim.x + threadIdx.x;
    if (t >= E + n) return;
    int src, dst;
    if (t < E) { src = ei[t]; dst = ei[E + t]; }
    else       { src = t - E; dst = src; }
    float sc = g_si[src] + g_sj[dst] + batt[0];
    sc = (sc >= 0.f) ? sc : 0.01f * sc;
    float e = expf(sc);
    int pos = atomicAdd(&g_cursor[src], 1);
    g_ds[pos] = dst;
    g_es[pos] = e;
}

// ---------------------------------------------------------------------------
// aggregation: warp per src node. Single pass: acc = sum e*h[dst], den = sum e,
// out = elu(acc/den). No atomics, coalesced write, fused ELU.
// ---------------------------------------------------------------------------
__global__ __launch_bounds__(256)
void aggregate_kernel(float* __restrict__ out, int n) {
    int w = (blockIdx.x * blockDim.x + threadIdx.x) >> 5;
    int lane = threadIdx.x & 31;
    if (w >= n) return;
    int s = g_off[w];
    int e = g_off[w + 1];

    float4 acc = make_float4(0.f, 0.f, 0.f, 0.f);
    float den = 0.f;

    int k = s;
    for (; k + 1 < e; k += 2) {
        float e0 = g_es[k], e1 = g_es[k + 1];
        int d0 = g_ds[k], d1 = g_ds[k + 1];
        float4 h0 = *(const float4*)&g_h[(size_t)d0 * D + lane * 4];
        float4 h1 = *(const float4*)&g_h[(size_t)d1 * D + lane * 4];
        acc.x += e0 * h0.x + e1 * h1.x;
        acc.y += e0 * h0.y + e1 * h1.y;
        acc.z += e0 * h0.z + e1 * h1.z;
        acc.w += e0 * h0.w + e1 * h1.w;
        den += e0 + e1;
    }
    if (k < e) {
        float e0 = g_es[k];
        int d0 = g_ds[k];
        float4 h0 = *(const float4*)&g_h[(size_t)d0 * D + lane * 4];
        acc.x += e0 * h0.x; acc.y += e0 * h0.y;
        acc.z += e0 * h0.z; acc.w += e0 * h0.w;
        den += e0;
    }

    float inv = 1.f / den;
    float4 o;
    o.x = acc.x * inv; o.y = acc.y * inv; o.z = acc.z * inv; o.w = acc.w * inv;
    o.x = (o.x > 0.f) ? o.x : expm1f(o.x);
    o.y = (o.y > 0.f) ? o.y : expm1f(o.y);
    o.z = (o.z > 0.f) ? o.z : expm1f(o.z);
    o.w = (o.w > 0.f) ? o.w : expm1f(o.w);
    *(float4*)&out[(size_t)w * D + lane * 4] = o;
}

// ---------------------------------------------------------------------------
extern "C" void kernel_launch(void* const* d_in, const int* in_sizes, int n_in,
                              void* d_out, int out_size) {
    const float* x    = (const float*)d_in[0];
    const int*   ei   = (const int*)  d_in[1];
    const float* W    = (const float*)d_in[2];
    const float* b    = (const float*)d_in[3];
    const float* Watt = (const float*)d_in[4];
    const float* batt = (const float*)d_in[5];
    float* out = (float*)d_out;

    int n = in_sizes[0] / D;
    int E = in_sizes[1] / 2;
    int total = E + n;
    int nb = (n + 1023) / 1024;

    init_kernel<<<(n + 255) / 256, 256>>>(n);
    gemm_kernel<<<(n + GBM - 1) / GBM, 256>>>(x, W, b, Watt, n);
    hist_kernel<<<(E + 255) / 256, 256>>>(ei, E);
    scan1_kernel<<<nb, 1024>>>(n);
    scan2_kernel<<<1, 32>>>(nb);
    scan3_kernel<<<(n + 255) / 256, 256>>>(n, total);
    scatter_kernel<<<(total + 255) / 256, 256>>>(ei, batt, E, n);
    aggregate_kernel<<<((long long)n * 32 + 255) / 256, 256>>>(out, n);
}

// round 4
// speedup vs baseline: 2.8054x; 1.1105x over previous
#include <cuda_runtime.h>
#include <cuda_bf16.h>
#include <cuda_fp16.h>
#include <cstdint>

#define MAX_N 100000
#define MAX_E 1600000
#define D 128
#define NB_MAX 128

// Scratch (device globals -- no allocation allowed)
__device__ __half g_hh[(size_t)MAX_N * D];     // 25.6 MB fp16 h, L2-resident
__device__ float g_si[MAX_N];
__device__ float g_sj[MAX_N];
__device__ int   g_cnt[MAX_N];
__device__ int   g_offp[MAX_N];
__device__ int   g_off[MAX_N + 1];
__device__ int   g_cursor[MAX_N];
__device__ int   g_bsum[NB_MAX];
__device__ int   g_bpre[NB_MAX];
__device__ uint2 g_de[MAX_E + MAX_N];          // packed (dst, exp(score))

// bit-reinterpret helpers
__device__ __forceinline__ unsigned h2_to_u32(__half2 h) {
    unsigned u; *reinterpret_cast<__half2*>(&u) = h; return u;
}
__device__ __forceinline__ __half2 u32_to_h2(unsigned u) {
    return *reinterpret_cast<__half2*>(&u);
}

// ---------------------------------------------------------------------------
__global__ void init_kernel(int n) {
    int i = blockIdx.x * blockDim.x + threadIdx.x;
    if (i < n) g_cnt[i] = 1;                   // self loop
}

// ---------------------------------------------------------------------------
// GEMM: h = x @ W^T + b (fp32 accum), epilogue: store fp16 h + fused s_i, s_j
// ---------------------------------------------------------------------------
#define GBM 128
#define GKT 16

__global__ __launch_bounds__(256, 2)
void gemm_kernel(const float* __restrict__ x, const float* __restrict__ W,
                 const float* __restrict__ b, const float* __restrict__ Watt,
                 int n) {
    __shared__ float xs[GKT][GBM + 4];
    __shared__ float ws[GKT][D + 4];

    int tid = threadIdx.x;
    int tx = tid & 15;
    int ty = tid >> 4;
    int row0 = blockIdx.x * GBM;

    float acc[8][8];
#pragma unroll
    for (int i = 0; i < 8; i++)
#pragma unroll
        for (int j = 0; j < 8; j++) acc[i][j] = 0.f;

    for (int kt = 0; kt < D; kt += GKT) {
#pragma unroll
        for (int r = 0; r < 2; r++) {
            int idx = tid + r * 256;
            int row = idx >> 2;
            int k4 = (idx & 3) * 4;
            float4 v = make_float4(0.f, 0.f, 0.f, 0.f);
            int gr = row0 + row;
            if (gr < n) v = *(const float4*)&x[(size_t)gr * D + kt + k4];
            xs[k4 + 0][row] = v.x; xs[k4 + 1][row] = v.y;
            xs[k4 + 2][row] = v.z; xs[k4 + 3][row] = v.w;
        }
#pragma unroll
        for (int r = 0; r < 2; r++) {
            int idx = tid + r * 256;
            int c = idx >> 2;
            int k4 = (idx & 3) * 4;
            float4 v = *(const float4*)&W[(size_t)c * D + kt + k4];
            ws[k4 + 0][c] = v.x; ws[k4 + 1][c] = v.y;
            ws[k4 + 2][c] = v.z; ws[k4 + 3][c] = v.w;
        }
        __syncthreads();

#pragma unroll
        for (int k = 0; k < GKT; k++) {
            float4 xa = *(const float4*)&xs[k][ty * 8];
            float4 xb = *(const float4*)&xs[k][ty * 8 + 4];
            float4 w0 = *(const float4*)&ws[k][tx * 4];
            float4 w1 = *(const float4*)&ws[k][64 + tx * 4];
            float xr[8] = {xa.x, xa.y, xa.z, xa.w, xb.x, xb.y, xb.z, xb.w};
            float wr[8] = {w0.x, w0.y, w0.z, w0.w, w1.x, w1.y, w1.z, w1.w};
#pragma unroll
            for (int i = 0; i < 8; i++)
#pragma unroll
                for (int j = 0; j < 8; j++) acc[i][j] += xr[i] * wr[j];
        }
        __syncthreads();
    }

    float4 b0  = *(const float4*)&b[tx * 4];
    float4 b1  = *(const float4*)&b[64 + tx * 4];
    float4 ai0 = *(const float4*)&Watt[tx * 4];
    float4 ai1 = *(const float4*)&Watt[64 + tx * 4];
    float4 aj0 = *(const float4*)&Watt[D + tx * 4];
    float4 aj1 = *(const float4*)&Watt[D + 64 + tx * 4];

#pragma unroll
    for (int i = 0; i < 8; i++) {
        int row = row0 + ty * 8 + i;
        if (row >= n) continue;
        float4 h0 = make_float4(acc[i][0] + b0.x, acc[i][1] + b0.y,
                                acc[i][2] + b0.z, acc[i][3] + b0.w);
        float4 h1 = make_float4(acc[i][4] + b1.x, acc[i][5] + b1.y,
                                acc[i][6] + b1.z, acc[i][7] + b1.w);
        // fp16 store (8 halves = two 8B stores)
        unsigned p0 = h2_to_u32(__floats2half2_rn(h0.x, h0.y));
        unsigned p1 = h2_to_u32(__floats2half2_rn(h0.z, h0.w));
        unsigned p2 = h2_to_u32(__floats2half2_rn(h1.x, h1.y));
        unsigned p3 = h2_to_u32(__floats2half2_rn(h1.z, h1.w));
        *(uint2*)&g_hh[(size_t)row * D + tx * 4] = make_uint2(p0, p1);
        *(uint2*)&g_hh[(size_t)row * D + 64 + tx * 4] = make_uint2(p2, p3);

        float psi = h0.x*ai0.x + h0.y*ai0.y + h0.z*ai0.z + h0.w*ai0.w
                  + h1.x*ai1.x + h1.y*ai1.y + h1.z*ai1.z + h1.w*ai1.w;
        float psj = h0.x*aj0.x + h0.y*aj0.y + h0.z*aj0.z + h0.w*aj0.w
                  + h1.x*aj1.x + h1.y*aj1.y + h1.z*aj1.z + h1.w*aj1.w;
#pragma unroll
        for (int o = 8; o; o >>= 1) {
            psi += __shfl_down_sync(0xffffffffu, psi, o, 16);
            psj += __shfl_down_sync(0xffffffffu, psj, o, 16);
        }
        if (tx == 0) { g_si[row] = psi; g_sj[row] = psj; }
    }
}

// ---------------------------------------------------------------------------
__global__ void hist_kernel(const int* __restrict__ ei, int E) {
    int t = blockIdx.x * blockDim.x + threadIdx.x;
    if (t < E) atomicAdd(&g_cnt[ei[t]], 1);
}

// ---------------------------------------------------------------------------
__global__ void scan1_kernel(int n) {
    __shared__ int sh[1024];
    int i = blockIdx.x * 1024 + threadIdx.x;
    int v = (i < n) ? g_cnt[i] : 0;
    sh[threadIdx.x] = v;
    __syncthreads();
    for (int off = 1; off < 1024; off <<= 1) {
        int t = (threadIdx.x >= off) ? sh[threadIdx.x - off] : 0;
        __syncthreads();
        sh[threadIdx.x] += t;
        __syncthreads();
    }
    if (i < n) g_offp[i] = sh[threadIdx.x] - v;
    if (threadIdx.x == 1023) g_bsum[blockIdx.x] = sh[1023];
}

__global__ void scan2_kernel(int nb) {
    __shared__ int sh[NB_MAX];
    int t = threadIdx.x;
    int v = (t < nb) ? g_bsum[t] : 0;
    sh[t] = v;
    __syncthreads();
    for (int off = 1; off < NB_MAX; off <<= 1) {
        int u = (t >= off) ? sh[t - off] : 0;
        __syncthreads();
        sh[t] += u;
        __syncthreads();
    }
    if (t < nb) g_bpre[t] = sh[t] - v;
}

__global__ void scan3_kernel(int n, int total) {
    int i = blockIdx.x * blockDim.x + threadIdx.x;
    if (i < n) {
        int o = g_offp[i] + g_bpre[i >> 10];
        g_off[i] = o;
        g_cursor[i] = o;
    }
    if (i == 0) g_off[n] = total;
}

// ---------------------------------------------------------------------------
// scatter: score + exp + bucket placement, packed 8B write
// ---------------------------------------------------------------------------
__global__ void scatter_kernel(const int* __restrict__ ei,
                               const float* __restrict__ batt, int E, int n) {
    int t = blockIdx.x * blockDim.x + threadIdx.x;
    if (t >= E + n) return;
    int src, dst;
    if (t < E) { src = ei[t]; dst = ei[E + t]; }
    else       { src = t - E; dst = src; }
    float sc = g_si[src] + g_sj[dst] + batt[0];
    sc = (sc >= 0.f) ? sc : 0.01f * sc;
    float e = expf(sc);
    int pos = atomicAdd(&g_cursor[src], 1);
    g_de[pos] = make_uint2((unsigned)dst, __float_as_uint(e));
}

// ---------------------------------------------------------------------------
// aggregation: warp per src node, fp16 gather (8B per lane per edge),
// fp32 accumulate, fused normalize + ELU, coalesced write.
// ---------------------------------------------------------------------------
__global__ __launch_bounds__(256)
void aggregate_kernel(float* __restrict__ out, int n) {
    int w = (blockIdx.x * blockDim.x + threadIdx.x) >> 5;
    int lane = threadIdx.x & 31;
    if (w >= n) return;
    int s = g_off[w];
    int e = g_off[w + 1];

    float4 acc = make_float4(0.f, 0.f, 0.f, 0.f);
    float den = 0.f;

    int k = s;
    for (; k + 3 < e; k += 4) {
        uint2 de0 = g_de[k],     de1 = g_de[k + 1];
        uint2 de2 = g_de[k + 2], de3 = g_de[k + 3];
        uint2 r0 = *(const uint2*)&g_hh[(size_t)de0.x * D + lane * 4];
        uint2 r1 = *(const uint2*)&g_hh[(size_t)de1.x * D + lane * 4];
        uint2 r2 = *(const uint2*)&g_hh[(size_t)de2.x * D + lane * 4];
        uint2 r3 = *(const uint2*)&g_hh[(size_t)de3.x * D + lane * 4];
        float e0 = __uint_as_float(de0.y), e1 = __uint_as_float(de1.y);
        float e2 = __uint_as_float(de2.y), e3 = __uint_as_float(de3.y);
        float2 a0 = __half22float2(u32_to_h2(r0.x));
        float2 a1 = __half22float2(u32_to_h2(r0.y));
        acc.x += e0 * a0.x; acc.y += e0 * a0.y; acc.z += e0 * a1.x; acc.w += e0 * a1.y;
        a0 = __half22float2(u32_to_h2(r1.x));
        a1 = __half22float2(u32_to_h2(r1.y));
        acc.x += e1 * a0.x; acc.y += e1 * a0.y; acc.z += e1 * a1.x; acc.w += e1 * a1.y;
        a0 = __half22float2(u32_to_h2(r2.x));
        a1 = __half22float2(u32_to_h2(r2.y));
        acc.x += e2 * a0.x; acc.y += e2 * a0.y; acc.z += e2 * a1.x; acc.w += e2 * a1.y;
        a0 = __half22float2(u32_to_h2(r3.x));
        a1 = __half22float2(u32_to_h2(r3.y));
        acc.x += e3 * a0.x; acc.y += e3 * a0.y; acc.z += e3 * a1.x; acc.w += e3 * a1.y;
        den += (e0 + e1) + (e2 + e3);
    }
    for (; k < e; k++) {
        uint2 de0 = g_de[k];
        uint2 r0 = *(const uint2*)&g_hh[(size_t)de0.x * D + lane * 4];
        float e0 = __uint_as_float(de0.y);
        float2 a0 = __half22float2(u32_to_h2(r0.x));
        float2 a1 = __half22float2(u32_to_h2(r0.y));
        acc.x += e0 * a0.x; acc.y += e0 * a0.y; acc.z += e0 * a1.x; acc.w += e0 * a1.y;
        den += e0;
    }

    float inv = 1.f / den;
    float4 o;
    o.x = acc.x * inv; o.y = acc.y * inv; o.z = acc.z * inv; o.w = acc.w * inv;
    o.x = (o.x > 0.f) ? o.x : expm1f(o.x);
    o.y = (o.y > 0.f) ? o.y : expm1f(o.y);
    o.z = (o.z > 0.f) ? o.z : expm1f(o.z);
    o.w = (o.w > 0.f) ? o.w : expm1f(o.w);
    *(float4*)&out[(size_t)w * D + lane * 4] = o;
}

// ---------------------------------------------------------------------------
extern "C" void kernel_launch(void* const* d_in, const int* in_sizes, int n_in,
                              void* d_out, int out_size) {
    const float* x    = (const float*)d_in[0];
    const int*   ei   = (const int*)  d_in[1];
    const float* W    = (const float*)d_in[2];
    const float* b    = (const float*)d_in[3];
    const float* Watt = (const float*)d_in[4];
    const float* batt = (const float*)d_in[5];
    float* out = (float*)d_out;

    int n = in_sizes[0] / D;
    int E = in_sizes[1] / 2;
    int total = E + n;
    int nb = (n + 1023) / 1024;

    init_kernel<<<(n + 255) / 256, 256>>>(n);
    gemm_kernel<<<(n + GBM - 1) / GBM, 256>>>(x, W, b, Watt, n);
    hist_kernel<<<(E + 255) / 256, 256>>>(ei, E);
    scan1_kernel<<<nb, 1024>>>(n);
    scan2_kernel<<<1, NB_MAX>>>(nb);
    scan3_kernel<<<(n + 255) / 256, 256>>>(n, total);
    scatter_kernel<<<(total + 255) / 256, 256>>>(ei, batt, E, n);
    aggregate_kernel<<<((long long)n * 32 + 255) / 256, 256>>>(out, n);
}

// round 5
// speedup vs baseline: 3.8711x; 1.3799x over previous
#include <cuda_runtime.h>
#include <cuda_bf16.h>
#include <cuda_fp16.h>
#include <cstdint>

#define MAX_N 100000
#define MAX_E 1600000
#define D 128
#define NB_MAX 128

// Scratch (device globals -- no allocation allowed)
__device__ __half g_hh[(size_t)MAX_N * D];     // 25.6 MB fp16 h
__device__ float g_si[MAX_N];
__device__ float g_sj[MAX_N];
__device__ int   g_cnt[MAX_N];
__device__ int   g_offp[MAX_N];
__device__ int   g_off[MAX_N + 1];
__device__ int   g_cursor[MAX_N];
__device__ int   g_bsum[NB_MAX];
__device__ int   g_bpre[NB_MAX];
__device__ uint2 g_de[MAX_E + MAX_N];          // packed (dst, exp(score))

__device__ __forceinline__ unsigned h2_to_u32(__half2 h) {
    unsigned u; *reinterpret_cast<__half2*>(&u) = h; return u;
}
__device__ __forceinline__ __half2 u32_to_h2(unsigned u) {
    return *reinterpret_cast<__half2*>(&u);
}

// ---------------------------------------------------------------------------
__global__ void init_kernel(int n) {
    int i = blockIdx.x * blockDim.x + threadIdx.x;
    if (i < n) g_cnt[i] = 1;                   // self loop
}

// ---------------------------------------------------------------------------
// Tensor-core GEMM: h = x @ W^T + b via mma.sync m16n8k16 f16f16f32.
// Block tile 128x128, K chunked 2x64. 8 warps: 4 in M x 2 in N.
// Epilogue: stage h (fp16, +bias) in smem; coalesced store to g_hh + fused
// attention projections s_i, s_j with width-16 shuffle reduction.
// ---------------------------------------------------------------------------
#define KC 64                  // K chunk
#define XPITCH 72              // xs/ws row pitch in halves (64 + 8 pad)
#define HPITCH 136             // hs row pitch in halves (128 + 8 pad)

__global__ __launch_bounds__(256, 2)
void gemm_kernel(const float* __restrict__ x, const float* __restrict__ W,
                 const float* __restrict__ b, const float* __restrict__ Watt,
                 int n) {
    __shared__ __align__(16) char smem_raw[2 * 128 * XPITCH * 2]; // 36864 B
    __half (*xs)[XPITCH] = (__half(*)[XPITCH])smem_raw;
    __half (*ws)[XPITCH] = (__half(*)[XPITCH])(smem_raw + 128 * XPITCH * 2);
    __half (*hs)[HPITCH] = (__half(*)[HPITCH])smem_raw;   // epilogue reuse

    int tid = threadIdx.x;
    int wid = tid >> 5;
    int lane = tid & 31;
    int gid = lane >> 2;        // group id (row within fragment)
    int tig = lane & 3;         // thread in group (col pair)
    int wm = wid & 3;           // warp M index (4)
    int wn = wid >> 2;          // warp N index (2)
    int row0 = blockIdx.x * 128;

    float c[2][8][4];
#pragma unroll
    for (int mi = 0; mi < 2; mi++)
#pragma unroll
        for (int ni = 0; ni < 8; ni++)
#pragma unroll
            for (int r = 0; r < 4; r++) c[mi][ni][r] = 0.f;

#pragma unroll
    for (int kk = 0; kk < D; kk += KC) {
        // load x chunk: 128 rows x 64 cols fp32 -> fp16 smem
#pragma unroll
        for (int r = 0; r < 8; r++) {
            int idx = tid + r * 256;            // 0..2047 float4 slots
            int row = idx >> 4;
            int c4 = (idx & 15) * 4;
            float4 v = make_float4(0.f, 0.f, 0.f, 0.f);
            int gr = row0 + row;
            if (gr < n) v = *(const float4*)&x[(size_t)gr * D + kk + c4];
            unsigned p0 = h2_to_u32(__floats2half2_rn(v.x, v.y));
            unsigned p1 = h2_to_u32(__floats2half2_rn(v.z, v.w));
            *(uint2*)&xs[row][c4] = make_uint2(p0, p1);
        }
        // load W chunk: ws[c][k] = W[c][kk+k]
#pragma unroll
        for (int r = 0; r < 8; r++) {
            int idx = tid + r * 256;
            int cc = idx >> 4;
            int c4 = (idx & 15) * 4;
            float4 v = *(const float4*)&W[(size_t)cc * D + kk + c4];
            unsigned p0 = h2_to_u32(__floats2half2_rn(v.x, v.y));
            unsigned p1 = h2_to_u32(__floats2half2_rn(v.z, v.w));
            *(uint2*)&ws[cc][c4] = make_uint2(p0, p1);
        }
        __syncthreads();

#pragma unroll
        for (int ks = 0; ks < KC / 16; ks++) {
            int kb = ks * 16 + tig * 2;
            unsigned a[2][4];
#pragma unroll
            for (int mi = 0; mi < 2; mi++) {
                int ra = wm * 32 + mi * 16 + gid;
                a[mi][0] = *(const unsigned*)&xs[ra][kb];
                a[mi][1] = *(const unsigned*)&xs[ra + 8][kb];
                a[mi][2] = *(const unsigned*)&xs[ra][kb + 8];
                a[mi][3] = *(const unsigned*)&xs[ra + 8][kb + 8];
            }
#pragma unroll
            for (int ni = 0; ni < 8; ni++) {
                int cb = wn * 64 + ni * 8 + gid;
                unsigned b0 = *(const unsigned*)&ws[cb][kb];
                unsigned b1 = *(const unsigned*)&ws[cb][kb + 8];
#pragma unroll
                for (int mi = 0; mi < 2; mi++) {
                    asm volatile(
                        "mma.sync.aligned.m16n8k16.row.col.f32.f16.f16.f32 "
                        "{%0,%1,%2,%3}, {%4,%5,%6,%7}, {%8,%9}, {%0,%1,%2,%3};"
                        : "+f"(c[mi][ni][0]), "+f"(c[mi][ni][1]),
                          "+f"(c[mi][ni][2]), "+f"(c[mi][ni][3])
                        : "r"(a[mi][0]), "r"(a[mi][1]), "r"(a[mi][2]), "r"(a[mi][3]),
                          "r"(b0), "r"(b1));
                }
            }
        }
        __syncthreads();
    }

    // epilogue pass 1: +bias, fp16, stage in smem
#pragma unroll
    for (int mi = 0; mi < 2; mi++) {
#pragma unroll
        for (int ni = 0; ni < 8; ni++) {
            int rr = wm * 32 + mi * 16 + gid;
            int col = wn * 64 + ni * 8 + tig * 2;
            float bx = __ldg(&b[col]);
            float by = __ldg(&b[col + 1]);
            *(unsigned*)&hs[rr][col] =
                h2_to_u32(__floats2half2_rn(c[mi][ni][0] + bx, c[mi][ni][1] + by));
            *(unsigned*)&hs[rr + 8][col] =
                h2_to_u32(__floats2half2_rn(c[mi][ni][2] + bx, c[mi][ni][3] + by));
        }
    }
    __syncthreads();

    // epilogue pass 2: coalesced store + fused s_i/s_j
    int tx = tid & 15;          // 16 col-groups of 8 halves
    int tyr = tid >> 4;         // 16 rows per iteration
    float ai_r[8], aj_r[8];
#pragma unroll
    for (int j = 0; j < 8; j++) {
        ai_r[j] = __ldg(&Watt[tx * 8 + j]);
        aj_r[j] = __ldg(&Watt[D + tx * 8 + j]);
    }
#pragma unroll
    for (int it = 0; it < 8; it++) {
        int row = it * 16 + tyr;
        int gr = row0 + row;
        uint4 v = *(const uint4*)&hs[row][tx * 8];
        float2 f0 = __half22float2(u32_to_h2(v.x));
        float2 f1 = __half22float2(u32_to_h2(v.y));
        float2 f2 = __half22float2(u32_to_h2(v.z));
        float2 f3 = __half22float2(u32_to_h2(v.w));
        float psi = f0.x*ai_r[0] + f0.y*ai_r[1] + f1.x*ai_r[2] + f1.y*ai_r[3]
                  + f2.x*ai_r[4] + f2.y*ai_r[5] + f3.x*ai_r[6] + f3.y*ai_r[7];
        float psj = f0.x*aj_r[0] + f0.y*aj_r[1] + f1.x*aj_r[2] + f1.y*aj_r[3]
                  + f2.x*aj_r[4] + f2.y*aj_r[5] + f3.x*aj_r[6] + f3.y*aj_r[7];
#pragma unroll
        for (int o = 8; o; o >>= 1) {
            psi += __shfl_down_sync(0xffffffffu, psi, o, 16);
            psj += __shfl_down_sync(0xffffffffu, psj, o, 16);
        }
        if (gr < n) {
            *(uint4*)&g_hh[(size_t)gr * D + tx * 8] = v;
            if (tx == 0) { g_si[gr] = psi; g_sj[gr] = psj; }
        }
    }
}

// ---------------------------------------------------------------------------
__global__ void hist_kernel(const int* __restrict__ ei, int E) {
    int t = blockIdx.x * blockDim.x + threadIdx.x;
    if (t < E) atomicAdd(&g_cnt[ei[t]], 1);
}

// ---------------------------------------------------------------------------
__global__ void scan1_kernel(int n) {
    __shared__ int sh[1024];
    int i = blockIdx.x * 1024 + threadIdx.x;
    int v = (i < n) ? g_cnt[i] : 0;
    sh[threadIdx.x] = v;
    __syncthreads();
    for (int off = 1; off < 1024; off <<= 1) {
        int t = (threadIdx.x >= off) ? sh[threadIdx.x - off] : 0;
        __syncthreads();
        sh[threadIdx.x] += t;
        __syncthreads();
    }
    if (i < n) g_offp[i] = sh[threadIdx.x] - v;
    if (threadIdx.x == 1023) g_bsum[blockIdx.x] = sh[1023];
}

__global__ void scan2_kernel(int nb) {
    __shared__ int sh[NB_MAX];
    int t = threadIdx.x;
    int v = (t < nb) ? g_bsum[t] : 0;
    sh[t] = v;
    __syncthreads();
    for (int off = 1; off < NB_MAX; off <<= 1) {
        int u = (t >= off) ? sh[t - off] : 0;
        __syncthreads();
        sh[t] += u;
        __syncthreads();
    }
    if (t < nb) g_bpre[t] = sh[t] - v;
}

__global__ void scan3_kernel(int n, int total) {
    int i = blockIdx.x * blockDim.x + threadIdx.x;
    if (i < n) {
        int o = g_offp[i] + g_bpre[i >> 10];
        g_off[i] = o;
        g_cursor[i] = o;
    }
    if (i == 0) g_off[n] = total;
}

// ---------------------------------------------------------------------------
__global__ void scatter_kernel(const int* __restrict__ ei,
                               const float* __restrict__ batt, int E, int n) {
    int t = blockIdx.x * blockDim.x + threadIdx.x;
    if (t >= E + n) return;
    int src, dst;
    if (t < E) { src = ei[t]; dst = ei[E + t]; }
    else       { src = t - E; dst = src; }
    float sc = g_si[src] + g_sj[dst] + batt[0];
    sc = (sc >= 0.f) ? sc : 0.01f * sc;
    float e = expf(sc);
    int pos = atomicAdd(&g_cursor[src], 1);
    g_de[pos] = make_uint2((unsigned)dst, __float_as_uint(e));
}

// ---------------------------------------------------------------------------
__global__ __launch_bounds__(256)
void aggregate_kernel(float* __restrict__ out, int n) {
    int w = (blockIdx.x * blockDim.x + threadIdx.x) >> 5;
    int lane = threadIdx.x & 31;
    if (w >= n) return;
    int s = g_off[w];
    int e = g_off[w + 1];

    float4 acc = make_float4(0.f, 0.f, 0.f, 0.f);
    float den = 0.f;

    int k = s;
    for (; k + 3 < e; k += 4) {
        uint2 de0 = g_de[k],     de1 = g_de[k + 1];
        uint2 de2 = g_de[k + 2], de3 = g_de[k + 3];
        uint2 r0 = *(const uint2*)&g_hh[(size_t)de0.x * D + lane * 4];
        uint2 r1 = *(const uint2*)&g_hh[(size_t)de1.x * D + lane * 4];
        uint2 r2 = *(const uint2*)&g_hh[(size_t)de2.x * D + lane * 4];
        uint2 r3 = *(const uint2*)&g_hh[(size_t)de3.x * D + lane * 4];
        float e0 = __uint_as_float(de0.y), e1 = __uint_as_float(de1.y);
        float e2 = __uint_as_float(de2.y), e3 = __uint_as_float(de3.y);
        float2 a0 = __half22float2(u32_to_h2(r0.x));
        float2 a1 = __half22float2(u32_to_h2(r0.y));
        acc.x += e0 * a0.x; acc.y += e0 * a0.y; acc.z += e0 * a1.x; acc.w += e0 * a1.y;
        a0 = __half22float2(u32_to_h2(r1.x));
        a1 = __half22float2(u32_to_h2(r1.y));
        acc.x += e1 * a0.x; acc.y += e1 * a0.y; acc.z += e1 * a1.x; acc.w += e1 * a1.y;
        a0 = __half22float2(u32_to_h2(r2.x));
        a1 = __half22float2(u32_to_h2(r2.y));
        acc.x += e2 * a0.x; acc.y += e2 * a0.y; acc.z += e2 * a1.x; acc.w += e2 * a1.y;
        a0 = __half22float2(u32_to_h2(r3.x));
        a1 = __half22float2(u32_to_h2(r3.y));
        acc.x += e3 * a0.x; acc.y += e3 * a0.y; acc.z += e3 * a1.x; acc.w += e3 * a1.y;
        den += (e0 + e1) + (e2 + e3);
    }
    for (; k < e; k++) {
        uint2 de0 = g_de[k];
        uint2 r0 = *(const uint2*)&g_hh[(size_t)de0.x * D + lane * 4];
        float e0 = __uint_as_float(de0.y);
        float2 a0 = __half22float2(u32_to_h2(r0.x));
        float2 a1 = __half22float2(u32_to_h2(r0.y));
        acc.x += e0 * a0.x; acc.y += e0 * a0.y; acc.z += e0 * a1.x; acc.w += e0 * a1.y;
        den += e0;
    }

    float inv = 1.f / den;
    float4 o;
    o.x = acc.x * inv; o.y = acc.y * inv; o.z = acc.z * inv; o.w = acc.w * inv;
    o.x = (o.x > 0.f) ? o.x : expm1f(o.x);
    o.y = (o.y > 0.f) ? o.y : expm1f(o.y);
    o.z = (o.z > 0.f) ? o.z : expm1f(o.z);
    o.w = (o.w > 0.f) ? o.w : expm1f(o.w);
    *(float4*)&out[(size_t)w * D + lane * 4] = o;
}

// ---------------------------------------------------------------------------
extern "C" void kernel_launch(void* const* d_in, const int* in_sizes, int n_in,
                              void* d_out, int out_size) {
    const float* x    = (const float*)d_in[0];
    const int*   ei   = (const int*)  d_in[1];
    const float* W    = (const float*)d_in[2];
    const float* b    = (const float*)d_in[3];
    const float* Watt = (const float*)d_in[4];
    const float* batt = (const float*)d_in[5];
    float* out = (float*)d_out;

    int n = in_sizes[0] / D;
    int E = in_sizes[1] / 2;
    int total = E + n;
    int nb = (n + 1023) / 1024;

    init_kernel<<<(n + 255) / 256, 256>>>(n);
    gemm_kernel<<<(n + 127) / 128, 256>>>(x, W, b, Watt, n);
    hist_kernel<<<(E + 255) / 256, 256>>>(ei, E);
    scan1_kernel<<<nb, 1024>>>(n);
    scan2_kernel<<<1, NB_MAX>>>(nb);
    scan3_kernel<<<(n + 255) / 256, 256>>>(n, total);
    scatter_kernel<<<(total + 255) / 256, 256>>>(ei, batt, E, n);
    aggregate_kernel<<<((long long)n * 32 + 255) / 256, 256>>>(out, n);
}